// round 3
// baseline (speedup 1.0000x reference)
#include <cuda_runtime.h>
#include <cuda_bf16.h>
#include <mma.h>

using namespace nvcuda;

// Problem constants: N=50000, D_IN=256, D_OUT=128, DEG=16
#define D_IN   256
#define D_OUT  128
#define MAX_N  50000
#define PAD_N  50048   // multiple of 64 so GEMM stores need no tail guard

// Scratch for Xp = X @ W — __device__ global, no allocation. Rows >= M are
// garbage but never read (column indices < M).
__device__ float g_Xp[(size_t)PAD_N * D_OUT];

// ---------------------------------------------------------------------------
// Kernel 1: 3xTF32 GEMM  Xp[M x 128] = A[M x 256] * B[256 x 128]
// Split-precision tf32 on tensor cores: A=Ah+Al, B=Bh+Bl,
//   C = Ah*Bh + Al*Bh + Ah*Bl   (error ~2^-22, fp32-grade)
// Block: 64 rows x 128 cols, 8 warps (4 in M x 2 in N), warp tile 16x64.
// ---------------------------------------------------------------------------
#define BM 64
#define BN 128
#define BK 32

__global__ __launch_bounds__(256, 2)
void gemm_tf32_kernel(const float* __restrict__ A, const float* __restrict__ B, int M) {
    __shared__ float As[BM][BK];   // fp32 staged; split to tf32 at fragment level
    __shared__ float Bs[BK][BN];

    const int tid    = threadIdx.x;
    const int wid    = tid >> 5;
    const int m0     = blockIdx.x * BM;
    const int warp_m = wid >> 1;   // 0..3 -> 16-row slab
    const int warp_n = wid & 1;    // 0..1 -> 64-col slab

    wmma::fragment<wmma::accumulator, 16, 16, 8, float> acc[4];
#pragma unroll
    for (int j = 0; j < 4; j++) wmma::fill_fragment(acc[j], 0.f);

    for (int k0 = 0; k0 < D_IN; k0 += BK) {
        // ---- stage A tile: 64x32 fp32 = 512 float4, 2 per thread
#pragma unroll
        for (int t = 0; t < 2; t++) {
            int i = tid + t * 256;          // 0..511
            int r = i >> 3;                 // 8 float4 per row
            int c = (i & 7) * 4;
            float4 v = make_float4(0.f, 0.f, 0.f, 0.f);
            if (m0 + r < M)
                v = *reinterpret_cast<const float4*>(&A[(size_t)(m0 + r) * D_IN + k0 + c]);
            *reinterpret_cast<float4*>(&As[r][c]) = v;
        }
        // ---- stage B tile: 32x128 fp32 = 1024 float4, 4 per thread
#pragma unroll
        for (int t = 0; t < 4; t++) {
            int i = tid + t * 256;          // 0..1023
            int r = i >> 5;                 // 32 float4 per row
            int c = (i & 31) * 4;
            *reinterpret_cast<float4*>(&Bs[r][c]) =
                *reinterpret_cast<const float4*>(&B[(size_t)(k0 + r) * D_OUT + c]);
        }
        __syncthreads();

#pragma unroll
        for (int kk = 0; kk < BK; kk += 8) {
            wmma::fragment<wmma::matrix_a, 16, 16, 8, wmma::precision::tf32, wmma::row_major> a_hi, a_lo;
            {
                wmma::fragment<wmma::matrix_a, 16, 16, 8, wmma::precision::tf32, wmma::row_major> a_raw;
                wmma::load_matrix_sync(a_raw, &As[warp_m * 16][kk], BK);
#pragma unroll
                for (int t = 0; t < a_raw.num_elements; t++) {
                    float v = a_raw.x[t];
                    float h = wmma::__float_to_tf32(v);
                    a_hi.x[t] = h;
                    a_lo.x[t] = wmma::__float_to_tf32(v - h);
                }
            }
#pragma unroll
            for (int j = 0; j < 4; j++) {
                wmma::fragment<wmma::matrix_b, 16, 16, 8, wmma::precision::tf32, wmma::row_major> b_hi, b_lo;
                {
                    wmma::fragment<wmma::matrix_b, 16, 16, 8, wmma::precision::tf32, wmma::row_major> b_raw;
                    wmma::load_matrix_sync(b_raw, &Bs[kk][warp_n * 64 + j * 16], BN);
#pragma unroll
                    for (int t = 0; t < b_raw.num_elements; t++) {
                        float v = b_raw.x[t];
                        float h = wmma::__float_to_tf32(v);
                        b_hi.x[t] = h;
                        b_lo.x[t] = wmma::__float_to_tf32(v - h);
                    }
                }
                // low-order corrections first, big term last
                wmma::mma_sync(acc[j], a_lo, b_hi, acc[j]);
                wmma::mma_sync(acc[j], a_hi, b_lo, acc[j]);
                wmma::mma_sync(acc[j], a_hi, b_hi, acc[j]);
            }
        }
        __syncthreads();
    }

    // ---- store warp tile (scratch is padded: no row guard needed)
    const int row = m0 + warp_m * 16;
#pragma unroll
    for (int j = 0; j < 4; j++) {
        float* dst = &g_Xp[(size_t)row * D_OUT + warp_n * 64 + j * 16];
        wmma::store_matrix_sync(dst, acc[j], D_OUT, wmma::mem_row_major);
    }
}

// ---------------------------------------------------------------------------
// Kernel 2: SpMM  out[i] = sum_{e in row i} Xp[col[e]]
// One warp per row; lane owns one float4 (4 of 128 cols). Unroll-by-8 for MLP.
// ---------------------------------------------------------------------------
__global__ __launch_bounds__(256)
void spmm_kernel(const int* __restrict__ rowptr, const int* __restrict__ colidx,
                 float* __restrict__ out, int M) {
    const int warp = (blockIdx.x * blockDim.x + threadIdx.x) >> 5;
    const int lane = threadIdx.x & 31;
    if (warp >= M) return;

    const int start = __ldg(&rowptr[warp]);
    const int end   = __ldg(&rowptr[warp + 1]);

    const float4* __restrict__ Xp4 = reinterpret_cast<const float4*>(g_Xp);

    float4 acc = make_float4(0.f, 0.f, 0.f, 0.f);
    int e = start;
    for (; e + 8 <= end; e += 8) {
        int c0 = __ldg(&colidx[e + 0]);
        int c1 = __ldg(&colidx[e + 1]);
        int c2 = __ldg(&colidx[e + 2]);
        int c3 = __ldg(&colidx[e + 3]);
        int c4 = __ldg(&colidx[e + 4]);
        int c5 = __ldg(&colidx[e + 5]);
        int c6 = __ldg(&colidx[e + 6]);
        int c7 = __ldg(&colidx[e + 7]);
        float4 v0 = Xp4[(size_t)c0 * 32 + lane];
        float4 v1 = Xp4[(size_t)c1 * 32 + lane];
        float4 v2 = Xp4[(size_t)c2 * 32 + lane];
        float4 v3 = Xp4[(size_t)c3 * 32 + lane];
        float4 v4 = Xp4[(size_t)c4 * 32 + lane];
        float4 v5 = Xp4[(size_t)c5 * 32 + lane];
        float4 v6 = Xp4[(size_t)c6 * 32 + lane];
        float4 v7 = Xp4[(size_t)c7 * 32 + lane];
        acc.x += (v0.x + v1.x) + (v2.x + v3.x) + (v4.x + v5.x) + (v6.x + v7.x);
        acc.y += (v0.y + v1.y) + (v2.y + v3.y) + (v4.y + v5.y) + (v6.y + v7.y);
        acc.z += (v0.z + v1.z) + (v2.z + v3.z) + (v4.z + v5.z) + (v6.z + v7.z);
        acc.w += (v0.w + v1.w) + (v2.w + v3.w) + (v4.w + v5.w) + (v6.w + v7.w);
    }
    for (; e < end; e++) {
        int c = __ldg(&colidx[e]);
        float4 v = Xp4[(size_t)c * 32 + lane];
        acc.x += v.x; acc.y += v.y; acc.z += v.z; acc.w += v.w;
    }

    reinterpret_cast<float4*>(out)[(size_t)warp * 32 + lane] = acc;
}

// ---------------------------------------------------------------------------
// Launch. Inputs (metadata order): X, weights, row_pointers, column_index, ...
// ---------------------------------------------------------------------------
extern "C" void kernel_launch(void* const* d_in, const int* in_sizes, int n_in,
                              void* d_out, int out_size) {
    const float* X  = (const float*)d_in[0];
    const float* W  = (const float*)d_in[1];
    const int*   rp = (const int*)d_in[2];
    const int*   ci = (const int*)d_in[3];
    float* out = (float*)d_out;

    const int M = in_sizes[0] / D_IN;   // 50000

    dim3 gemm_grid((M + BM - 1) / BM);
    gemm_tf32_kernel<<<gemm_grid, 256>>>(X, W, M);

    const int warps_per_block = 256 / 32;
    dim3 spmm_grid((M + warps_per_block - 1) / warps_per_block);
    spmm_kernel<<<spmm_grid, 256>>>(rp, ci, out, M);
}

// round 5
// speedup vs baseline: 1.5050x; 1.5050x over previous
#include <cuda_runtime.h>
#include <cstdint>

// Problem constants: N=50000, D_IN=256, D_OUT=128, DEG=16
#define D_IN   256
#define D_OUT  128
#define PAD_N  50048   // 391 * 128, so GEMM stores need no tail guard

// Scratch for Xp = X @ W — __device__ global, no allocation. Rows >= M are
// garbage but never read (column indices < M).
__device__ __align__(16) float g_Xp[(size_t)PAD_N * D_OUT];

// ---------------------------------------------------------------------------
// Packed f32x2 helpers (sm_100+ base PTX; ptxas keeps FFMA2 in SASS)
// ---------------------------------------------------------------------------
__device__ __forceinline__ unsigned long long pack_dup(float a) {
    unsigned long long r;
    asm("mov.b64 %0, {%1, %1};" : "=l"(r) : "f"(a));
    return r;
}
__device__ __forceinline__ void fma2(unsigned long long& acc,
                                     unsigned long long a, unsigned long long b) {
    asm("fma.rn.f32x2 %0, %1, %2, %0;" : "+l"(acc) : "l"(a), "l"(b));
}
__device__ __forceinline__ void unpack2(float& lo, float& hi, unsigned long long v) {
    asm("mov.b64 {%0, %1}, %2;" : "=f"(lo), "=f"(hi) : "l"(v));
}

// ---------------------------------------------------------------------------
// Kernel 1: f32x2 SGEMM  Xp[M x 128] = A[M x 256] * B[256 x 128]
// BM=128, BN=128, BK=32; 256 threads; 8x8 micro-tile as 8x4 packed pairs.
// ---------------------------------------------------------------------------
#define BM  128
#define BN  128
#define BKK 32
#define ASTRIDE (BM + 4)   // pad: 4-way worst-case on transposed stores

__global__ __launch_bounds__(256, 2)
void gemm_f32x2_kernel(const float* __restrict__ A, const float* __restrict__ B, int M) {
    __shared__ float As[BKK][ASTRIDE];   // transposed A tile
    __shared__ float Bs[BKK][BN];

    const int tid = threadIdx.x;         // 0..255
    const int m0  = blockIdx.x * BM;
    const int ty  = tid >> 4;            // 0..15 -> 8-row slab
    const int tx  = tid & 15;            // 0..15 -> 8-col slab

    unsigned long long acc[8][4];        // [m][n-pair], each = (c_{2j}, c_{2j+1})
#pragma unroll
    for (int i = 0; i < 8; i++)
#pragma unroll
        for (int j = 0; j < 4; j++) acc[i][j] = 0ull;   // bits of (+0.f, +0.f)

    for (int k0 = 0; k0 < D_IN; k0 += BKK) {
        // ---- stage A tile 128x32 (1024 float4, 4/thread), store transposed
#pragma unroll
        for (int t = 0; t < 4; t++) {
            int i  = tid + t * 256;      // 0..1023
            int r  = i >> 3;             // row 0..127
            int c4 = i & 7;              // float4 along K
            float4 v = make_float4(0.f, 0.f, 0.f, 0.f);
            if (m0 + r < M)
                v = *reinterpret_cast<const float4*>(&A[(size_t)(m0 + r) * D_IN + k0 + c4 * 4]);
            As[c4 * 4 + 0][r] = v.x;
            As[c4 * 4 + 1][r] = v.y;
            As[c4 * 4 + 2][r] = v.z;
            As[c4 * 4 + 3][r] = v.w;
        }
        // ---- stage B tile 32x128 (1024 float4, 4/thread)
#pragma unroll
        for (int t = 0; t < 4; t++) {
            int i = tid + t * 256;       // 0..1023
            int r = i >> 5;              // 0..31
            int c = (i & 31) * 4;
            *reinterpret_cast<float4*>(&Bs[r][c]) =
                *reinterpret_cast<const float4*>(&B[(size_t)(k0 + r) * D_OUT + c]);
        }
        __syncthreads();

#pragma unroll
        for (int k = 0; k < BKK; k++) {
            // a: 8 rows, duplicated into both f32x2 lanes
            float4 a0 = *reinterpret_cast<const float4*>(&As[k][ty * 8]);
            float4 a1 = *reinterpret_cast<const float4*>(&As[k][ty * 8 + 4]);
            unsigned long long a2[8];
            a2[0] = pack_dup(a0.x); a2[1] = pack_dup(a0.y);
            a2[2] = pack_dup(a0.z); a2[3] = pack_dup(a0.w);
            a2[4] = pack_dup(a1.x); a2[5] = pack_dup(a1.y);
            a2[6] = pack_dup(a1.z); a2[7] = pack_dup(a1.w);
            // b: 4 column-pairs, already packed in memory
            ulonglong2 bb0 = *reinterpret_cast<const ulonglong2*>(&Bs[k][tx * 8]);
            ulonglong2 bb1 = *reinterpret_cast<const ulonglong2*>(&Bs[k][tx * 8 + 4]);
            unsigned long long b2[4] = {bb0.x, bb0.y, bb1.x, bb1.y};
#pragma unroll
            for (int i = 0; i < 8; i++) {
#pragma unroll
                for (int j = 0; j < 4; j++)
                    fma2(acc[i][j], a2[i], b2[j]);
            }
        }
        __syncthreads();
    }

    // ---- store 8x8 micro-tile (scratch padded: no row guard)
#pragma unroll
    for (int i = 0; i < 8; i++) {
        const int row = m0 + ty * 8 + i;
        float r[8];
#pragma unroll
        for (int j = 0; j < 4; j++) unpack2(r[2 * j], r[2 * j + 1], acc[i][j]);
        float4* dst = reinterpret_cast<float4*>(&g_Xp[(size_t)row * D_OUT + tx * 8]);
        dst[0] = make_float4(r[0], r[1], r[2], r[3]);
        dst[1] = make_float4(r[4], r[5], r[6], r[7]);
    }
}

// ---------------------------------------------------------------------------
// Kernel 2: SpMM  out[i] = sum_{e in row i} Xp[col[e]]
// One warp per row; lane owns one float4 (4 of 128 cols). Unroll-by-8 for MLP.
// ---------------------------------------------------------------------------
__global__ void __launch_bounds__(256)
spmm_kernel(const int* __restrict__ rowptr, const int* __restrict__ colidx,
            float* __restrict__ out, int M) {
    const int warp = (blockIdx.x * blockDim.x + threadIdx.x) >> 5;
    const int lane = threadIdx.x & 31;
    if (warp >= M) return;

    const int start = __ldg(&rowptr[warp]);
    const int end   = __ldg(&rowptr[warp + 1]);

    const float4* __restrict__ Xp4 = reinterpret_cast<const float4*>(g_Xp);

    float4 acc = make_float4(0.f, 0.f, 0.f, 0.f);
    int e = start;
    for (; e + 8 <= end; e += 8) {
        int c0 = __ldg(&colidx[e + 0]);
        int c1 = __ldg(&colidx[e + 1]);
        int c2 = __ldg(&colidx[e + 2]);
        int c3 = __ldg(&colidx[e + 3]);
        int c4 = __ldg(&colidx[e + 4]);
        int c5 = __ldg(&colidx[e + 5]);
        int c6 = __ldg(&colidx[e + 6]);
        int c7 = __ldg(&colidx[e + 7]);
        float4 v0 = Xp4[(size_t)c0 * 32 + lane];
        float4 v1 = Xp4[(size_t)c1 * 32 + lane];
        float4 v2 = Xp4[(size_t)c2 * 32 + lane];
        float4 v3 = Xp4[(size_t)c3 * 32 + lane];
        float4 v4 = Xp4[(size_t)c4 * 32 + lane];
        float4 v5 = Xp4[(size_t)c5 * 32 + lane];
        float4 v6 = Xp4[(size_t)c6 * 32 + lane];
        float4 v7 = Xp4[(size_t)c7 * 32 + lane];
        acc.x += (v0.x + v1.x) + (v2.x + v3.x) + (v4.x + v5.x) + (v6.x + v7.x);
        acc.y += (v0.y + v1.y) + (v2.y + v3.y) + (v4.y + v5.y) + (v6.y + v7.y);
        acc.z += (v0.z + v1.z) + (v2.z + v3.z) + (v4.z + v5.z) + (v6.z + v7.z);
        acc.w += (v0.w + v1.w) + (v2.w + v3.w) + (v4.w + v5.w) + (v6.w + v7.w);
    }
    for (; e < end; e++) {
        int c = __ldg(&colidx[e]);
        float4 v = Xp4[(size_t)c * 32 + lane];
        acc.x += v.x; acc.y += v.y; acc.z += v.z; acc.w += v.w;
    }

    reinterpret_cast<float4*>(out)[(size_t)warp * 32 + lane] = acc;
}

// ---------------------------------------------------------------------------
// Launch. Inputs (metadata order): X, weights, row_pointers, column_index, ...
// ---------------------------------------------------------------------------
extern "C" void kernel_launch(void* const* d_in, const int* in_sizes, int n_in,
                              void* d_out, int out_size) {
    const float* X  = (const float*)d_in[0];
    const float* W  = (const float*)d_in[1];
    const int*   rp = (const int*)d_in[2];
    const int*   ci = (const int*)d_in[3];
    float* out = (float*)d_out;

    const int M = in_sizes[0] / D_IN;   // 50000

    dim3 gemm_grid((M + BM - 1) / BM);  // 391
    gemm_f32x2_kernel<<<gemm_grid, 256>>>(X, W, M);

    const int warps_per_block = 256 / 32;
    dim3 spmm_grid((M + warps_per_block - 1) / warps_per_block);
    spmm_kernel<<<spmm_grid, 256>>>(rp, ci, out, M);
}